// round 15
// baseline (speedup 1.0000x reference)
#include <cuda_runtime.h>

#define D 64
#define MAXN 50000
#define MAXE 800000
#define MAXG 512
#define MAXV 128

typedef unsigned long long u64;

// ---------------- scratch (device globals; no allocation) ----------------
__device__ __align__(128) float g_embW[MAXV * D];
__device__ __align__(128) float g_h1[MAXN * D];
__device__ __align__(128) float g_nb[MAXN * D];   // SAGE mean; later GIN t-stage scratch
__device__ __align__(128) float g_h2[MAXN * D];
__device__ __align__(128) float g_z[MAXN * D];
__device__ __align__(128) float g_h3[MAXN * D];
// CSR build
__device__ __align__(128) int g_deg[MAXN];     // zeroed by k_scan after use
__device__ __align__(128) int g_off[MAXN + 8];
__device__ __align__(128) int g_cursor[MAXN];
__device__ __align__(128) int2 g_sx[MAXE];     // {src, x[src]} per CSR slot

__device__ __forceinline__ float4 f4add(float4 a, float4 b) {
    return make_float4(a.x + b.x, a.y + b.y, a.z + b.z, a.w + b.w);
}

// packed f32x2 helpers (Blackwell)
__device__ __forceinline__ u64 pack2s(float x) {
    u64 r; asm("mov.b64 %0, {%1,%1};" : "=l"(r) : "f"(x)); return r;
}
__device__ __forceinline__ u64 pack2(float x, float y) {
    u64 r; asm("mov.b64 %0, {%1,%2};" : "=l"(r) : "f"(x), "f"(y)); return r;
}
__device__ __forceinline__ void ffma2(u64& d, u64 a, u64 b) {
    asm("fma.rn.f32x2 %0, %1, %2, %3;" : "=l"(d) : "l"(a), "l"(b), "l"(d));
}
__device__ __forceinline__ float2 unpack2(u64 v) {
    float2 f; asm("mov.b64 {%0,%1}, %2;" : "=f"(f.x), "=f"(f.y) : "l"(v)); return f;
}

// ---------------- pre: embW = emb@W + degree histogram (8 edges/thread) ----------------
__global__ void k_pre(const int* __restrict__ ei, const float* __restrict__ emb,
                      const float* __restrict__ W, int Vn, int E_) {
    int gid = blockIdx.x * blockDim.x + threadIdx.x;
    int stride = gridDim.x * blockDim.x;
    for (int idx = gid; idx < Vn * D; idx += stride) {
        int v = idx >> 6, j = idx & 63;
        float s = 0.f;
#pragma unroll
        for (int k = 0; k < D; k++) s += emb[v * D + k] * W[k * D + j];
        g_embW[idx] = s;
    }
    if ((E_ & 3) == 0) {
        for (int base = gid * 8; base < E_; base += stride * 8) {
            if (base + 7 < E_) {
                int4 d0 = *reinterpret_cast<const int4*>(ei + E_ + base);
                int4 d1 = *reinterpret_cast<const int4*>(ei + E_ + base + 4);
                atomicAdd(&g_deg[d0.x], 1);
                atomicAdd(&g_deg[d0.y], 1);
                atomicAdd(&g_deg[d0.z], 1);
                atomicAdd(&g_deg[d0.w], 1);
                atomicAdd(&g_deg[d1.x], 1);
                atomicAdd(&g_deg[d1.y], 1);
                atomicAdd(&g_deg[d1.z], 1);
                atomicAdd(&g_deg[d1.w], 1);
            } else {
#pragma unroll
                for (int u = 0; u < 8; u++) {
                    int e = base + u;
                    if (e < E_) atomicAdd(&g_deg[__ldg(&ei[E_ + e])], 1);
                }
            }
        }
    } else {
        for (int base = gid * 8; base < E_; base += stride * 8) {
#pragma unroll
            for (int u = 0; u < 8; u++) {
                int e = base + u;
                if (e < E_) atomicAdd(&g_deg[__ldg(&ei[E_ + e])], 1);
            }
        }
    }
}

// ---------------- single-block exclusive scan (8 elems/thread, 8192/iter) ----------------
__global__ void __launch_bounds__(1024) k_scan(int n) {
    __shared__ int wsum[32];
    __shared__ int s_total;
    int tid = threadIdx.x, lane = tid & 31, warp = tid >> 5;
    int carry = 0;
    for (int base = 0; base < n; base += 8192) {
        int i8 = base + tid * 8;
        int va[8];
#pragma unroll
        for (int u = 0; u < 8; u++) va[u] = 0;
        if (i8 + 7 < n) {
            int4 lo = *reinterpret_cast<const int4*>(g_deg + i8);
            int4 hi = *reinterpret_cast<const int4*>(g_deg + i8 + 4);
            va[0] = lo.x; va[1] = lo.y; va[2] = lo.z; va[3] = lo.w;
            va[4] = hi.x; va[5] = hi.y; va[6] = hi.z; va[7] = hi.w;
        } else if (i8 < n) {
#pragma unroll
            for (int u = 0; u < 8; u++)
                if (i8 + u < n) va[u] = g_deg[i8 + u];
        }
        int sum = 0;
#pragma unroll
        for (int u = 0; u < 8; u++) sum += va[u];
        int inc = sum;
#pragma unroll
        for (int off = 1; off < 32; off <<= 1) {
            int tv = __shfl_up_sync(0xffffffffu, inc, off);
            if (lane >= off) inc += tv;
        }
        if (lane == 31) wsum[warp] = inc;
        __syncthreads();
        if (warp == 0) {
            int w = wsum[lane];
            int wi = w;
#pragma unroll
            for (int off = 1; off < 32; off <<= 1) {
                int tv = __shfl_up_sync(0xffffffffu, wi, off);
                if (lane >= off) wi += tv;
            }
            wsum[lane] = wi - w;
            if (lane == 31) s_total = wi;
        }
        __syncthreads();
        int o[8];
        o[0] = carry + inc - sum + wsum[warp];
#pragma unroll
        for (int u = 1; u < 8; u++) o[u] = o[u - 1] + va[u - 1];
        if (i8 + 7 < n) {
            *reinterpret_cast<int4*>(g_off + i8) = make_int4(o[0], o[1], o[2], o[3]);
            *reinterpret_cast<int4*>(g_off + i8 + 4) = make_int4(o[4], o[5], o[6], o[7]);
            *reinterpret_cast<int4*>(g_cursor + i8) = make_int4(o[0], o[1], o[2], o[3]);
            *reinterpret_cast<int4*>(g_cursor + i8 + 4) = make_int4(o[4], o[5], o[6], o[7]);
            *reinterpret_cast<int4*>(g_deg + i8) = make_int4(0, 0, 0, 0);
            *reinterpret_cast<int4*>(g_deg + i8 + 4) = make_int4(0, 0, 0, 0);
        } else if (i8 < n) {
#pragma unroll
            for (int u = 0; u < 8; u++) {
                if (i8 + u < n) { g_off[i8 + u] = o[u]; g_cursor[i8 + u] = o[u]; g_deg[i8 + u] = 0; }
            }
        }
        carry += s_total;
        __syncthreads();
    }
    if (tid == 0) g_off[n] = carry;
}

// ---------------- scatter: interleaved CSR {src, x[src]} (8 edges/thread) ----------------
__global__ void k_scatter(const int* __restrict__ ei, const int* __restrict__ x, int E_) {
    int e0 = (blockIdx.x * blockDim.x + threadIdx.x) * 8;
    if ((E_ & 3) == 0 && e0 + 7 < E_) {
        int4 s0 = *reinterpret_cast<const int4*>(ei + e0);
        int4 s1 = *reinterpret_cast<const int4*>(ei + e0 + 4);
        int4 d0 = *reinterpret_cast<const int4*>(ei + E_ + e0);
        int4 d1 = *reinterpret_cast<const int4*>(ei + E_ + e0 + 4);
        int x0 = __ldg(&x[s0.x]);
        int x1 = __ldg(&x[s0.y]);
        int x2 = __ldg(&x[s0.z]);
        int x3 = __ldg(&x[s0.w]);
        int x4 = __ldg(&x[s1.x]);
        int x5 = __ldg(&x[s1.y]);
        int x6 = __ldg(&x[s1.z]);
        int x7 = __ldg(&x[s1.w]);
        int p0 = atomicAdd(&g_cursor[d0.x], 1);
        int p1 = atomicAdd(&g_cursor[d0.y], 1);
        int p2 = atomicAdd(&g_cursor[d0.z], 1);
        int p3 = atomicAdd(&g_cursor[d0.w], 1);
        int p4 = atomicAdd(&g_cursor[d1.x], 1);
        int p5 = atomicAdd(&g_cursor[d1.y], 1);
        int p6 = atomicAdd(&g_cursor[d1.z], 1);
        int p7 = atomicAdd(&g_cursor[d1.w], 1);
        g_sx[p0] = make_int2(s0.x, x0);
        g_sx[p1] = make_int2(s0.y, x1);
        g_sx[p2] = make_int2(s0.z, x2);
        g_sx[p3] = make_int2(s0.w, x3);
        g_sx[p4] = make_int2(s1.x, x4);
        g_sx[p5] = make_int2(s1.y, x5);
        g_sx[p6] = make_int2(s1.z, x6);
        g_sx[p7] = make_int2(s1.w, x7);
    } else {
#pragma unroll
        for (int u = 0; u < 8; u++) {
            int e = e0 + u;
            if (e < E_) {
                int src = __ldg(&ei[e]);
                int dst = __ldg(&ei[E_ + e]);
                int xv = __ldg(&x[src]);
                int pos = atomicAdd(&g_cursor[dst], 1);
                g_sx[pos] = make_int2(src, xv);
            }
        }
    }
}

// ---------------- GCN gather: h1[n] = relu(sum_nb embW[x[src]]) ----------------
__global__ void k_gather_gcn(int n_nodes) {
    int gid = blockIdx.x * blockDim.x + threadIdx.x;
    int node = gid >> 4, q = gid & 15;
    if (node >= n_nodes) return;
    int start = g_off[node];
    int cnt = g_off[node + 1] - start;
    const float4* embW4 = reinterpret_cast<const float4*>(g_embW);
    float4 acc = make_float4(0.f, 0.f, 0.f, 0.f);
    int t = 0;
    for (; t + 4 <= cnt; t += 4) {
        int2 i0 = __ldg(&g_sx[start + t + 0]);
        int2 i1 = __ldg(&g_sx[start + t + 1]);
        int2 i2 = __ldg(&g_sx[start + t + 2]);
        int2 i3 = __ldg(&g_sx[start + t + 3]);
        float4 v0 = embW4[i0.y * 16 + q];
        float4 v1 = embW4[i1.y * 16 + q];
        float4 v2 = embW4[i2.y * 16 + q];
        float4 v3 = embW4[i3.y * 16 + q];
        acc = f4add(acc, f4add(f4add(v0, v1), f4add(v2, v3)));
    }
    for (; t < cnt; t++) {
        int2 i0 = __ldg(&g_sx[start + t]);
        acc = f4add(acc, embW4[i0.y * 16 + q]);
    }
    acc.x = fmaxf(acc.x, 0.f); acc.y = fmaxf(acc.y, 0.f);
    acc.z = fmaxf(acc.z, 0.f); acc.w = fmaxf(acc.w, 0.f);
    reinterpret_cast<float4*>(g_h1 + node * D)[q] = acc;
}

// ---------------- SAGE gather: nb[n] = mean_nb h1[src] ----------------
__global__ void k_gather_mean(int n_nodes) {
    int gid = blockIdx.x * blockDim.x + threadIdx.x;
    int node = gid >> 4, q = gid & 15;
    if (node >= n_nodes) return;
    int start = g_off[node];
    int cnt = g_off[node + 1] - start;
    float4 acc = make_float4(0.f, 0.f, 0.f, 0.f);
    int t = 0;
    for (; t + 4 <= cnt; t += 4) {
        int2 i0 = __ldg(&g_sx[start + t + 0]);
        int2 i1 = __ldg(&g_sx[start + t + 1]);
        int2 i2 = __ldg(&g_sx[start + t + 2]);
        int2 i3 = __ldg(&g_sx[start + t + 3]);
        float4 v0 = reinterpret_cast<const float4*>(g_h1 + i0.x * D)[q];
        float4 v1 = reinterpret_cast<const float4*>(g_h1 + i1.x * D)[q];
        float4 v2 = reinterpret_cast<const float4*>(g_h1 + i2.x * D)[q];
        float4 v3 = reinterpret_cast<const float4*>(g_h1 + i3.x * D)[q];
        acc = f4add(acc, f4add(f4add(v0, v1), f4add(v2, v3)));
    }
    for (; t < cnt; t++) {
        int2 i0 = __ldg(&g_sx[start + t]);
        acc = f4add(acc, reinterpret_cast<const float4*>(g_h1 + i0.x * D)[q]);
    }
    float invd = 1.0f / fmaxf((float)cnt, 1.0f);
    acc.x *= invd; acc.y *= invd; acc.z *= invd; acc.w *= invd;
    reinterpret_cast<float4*>(g_nb + node * D)[q] = acc;
}

// ---------------- GIN gather: z[n] = h2[n] + sum_nb h2[src] ----------------
__global__ void k_gather_gin(int n_nodes) {
    int gid = blockIdx.x * blockDim.x + threadIdx.x;
    int node = gid >> 4, q = gid & 15;
    if (node >= n_nodes) return;
    int start = g_off[node];
    int cnt = g_off[node + 1] - start;
    float4 acc = reinterpret_cast<const float4*>(g_h2 + node * D)[q];
    int t = 0;
    for (; t + 4 <= cnt; t += 4) {
        int2 i0 = __ldg(&g_sx[start + t + 0]);
        int2 i1 = __ldg(&g_sx[start + t + 1]);
        int2 i2 = __ldg(&g_sx[start + t + 2]);
        int2 i3 = __ldg(&g_sx[start + t + 3]);
        float4 v0 = reinterpret_cast<const float4*>(g_h2 + i0.x * D)[q];
        float4 v1 = reinterpret_cast<const float4*>(g_h2 + i1.x * D)[q];
        float4 v2 = reinterpret_cast<const float4*>(g_h2 + i2.x * D)[q];
        float4 v3 = reinterpret_cast<const float4*>(g_h2 + i3.x * D)[q];
        acc = f4add(acc, f4add(f4add(v0, v1), f4add(v2, v3)));
    }
    for (; t < cnt; t++) {
        int2 i0 = __ldg(&g_sx[start + t]);
        acc = f4add(acc, reinterpret_cast<const float4*>(g_h2 + i0.x * D)[q]);
    }
    reinterpret_cast<float4*>(g_z + node * D)[q] = acc;
}

// ---------------- SAGE GEMM: h2 = relu(nb @ Wl + h1 @ Wr) ----------------
__global__ void __launch_bounds__(256) k_sage(const float* __restrict__ Wl,
                                              const float* __restrict__ Wr, int n_nodes) {
    __shared__ ulonglong2 sWl[D * 16];
    __shared__ ulonglong2 sWr[D * 16];
    {
        const ulonglong2* wl2 = reinterpret_cast<const ulonglong2*>(Wl);
        const ulonglong2* wr2 = reinterpret_cast<const ulonglong2*>(Wr);
        for (int i = threadIdx.x; i < D * 16; i += blockDim.x) { sWl[i] = wl2[i]; sWr[i] = wr2[i]; }
    }
    __syncthreads();
    int lane = threadIdx.x & 31, warp = threadIdx.x >> 5;
    int ntiles = (n_nodes + 31) / 32;
    int nwarps = gridDim.x * 8;
    for (int tile = blockIdx.x * 8 + warp; tile < ntiles; tile += nwarps) {
        int n = tile * 32 + lane;
        bool valid = n < n_nodes;
        int nn = valid ? n : (n_nodes - 1);
        const float4* nb4 = reinterpret_cast<const float4*>(g_nb + nn * D);
        const float4* h4 = reinterpret_cast<const float4*>(g_h1 + nn * D);
        u64 acc[32];
#pragma unroll
        for (int j = 0; j < 32; j++) acc[j] = 0ULL;
        for (int kk = 0; kk < 16; kk++) {
            float4 anb = __ldg(nb4 + kk);
            float4 ah = __ldg(h4 + kk);
            float an[4] = {anb.x, anb.y, anb.z, anb.w};
            float av[4] = {ah.x, ah.y, ah.z, ah.w};
#pragma unroll
            for (int s = 0; s < 4; s++) {
                int k = kk * 4 + s;
                u64 pa = pack2s(an[s]);
                u64 ph = pack2s(av[s]);
#pragma unroll
                for (int jj = 0; jj < 16; jj++) {
                    ulonglong2 wl = sWl[k * 16 + jj];
                    ulonglong2 wr = sWr[k * 16 + jj];
                    ffma2(acc[2 * jj], pa, wl.x);
                    ffma2(acc[2 * jj], ph, wr.x);
                    ffma2(acc[2 * jj + 1], pa, wl.y);
                    ffma2(acc[2 * jj + 1], ph, wr.y);
                }
            }
        }
        if (valid) {
            float4* o = reinterpret_cast<float4*>(g_h2 + n * D);
#pragma unroll
            for (int jj = 0; jj < 16; jj++) {
                float2 p0 = unpack2(acc[2 * jj]);
                float2 p1 = unpack2(acc[2 * jj + 1]);
                o[jj] = make_float4(fmaxf(p0.x, 0.f), fmaxf(p0.y, 0.f),
                                    fmaxf(p1.x, 0.f), fmaxf(p1.y, 0.f));
            }
        }
    }
}

// ---------------- GIN GEMM: h3 = relu(relu(z@W1+b1)@W2+b2) ----------------
__global__ void __launch_bounds__(256) k_gin(const float* __restrict__ W1,
                                             const float* __restrict__ b1,
                                             const float* __restrict__ W2,
                                             const float* __restrict__ b2, int n_nodes) {
    __shared__ ulonglong2 sW1[D * 16];
    __shared__ ulonglong2 sW2[D * 16];
    {
        const ulonglong2* w12 = reinterpret_cast<const ulonglong2*>(W1);
        const ulonglong2* w22 = reinterpret_cast<const ulonglong2*>(W2);
        for (int i = threadIdx.x; i < D * 16; i += blockDim.x) { sW1[i] = w12[i]; sW2[i] = w22[i]; }
    }
    __syncthreads();
    int lane = threadIdx.x & 31, warp = threadIdx.x >> 5;
    int ntiles = (n_nodes + 31) / 32;
    int nwarps = gridDim.x * 8;
    const float4* b1v = reinterpret_cast<const float4*>(b1);
    const float4* b2v = reinterpret_cast<const float4*>(b2);
    for (int tile = blockIdx.x * 8 + warp; tile < ntiles; tile += nwarps) {
        int n = tile * 32 + lane;
        bool valid = n < n_nodes;
        int nn = valid ? n : (n_nodes - 1);
        const float4* z4 = reinterpret_cast<const float4*>(g_z + nn * D);
        u64 acc[32];
#pragma unroll
        for (int jj = 0; jj < 16; jj++) {
            float4 bb = __ldg(b1v + jj);
            acc[2 * jj] = pack2(bb.x, bb.y);
            acc[2 * jj + 1] = pack2(bb.z, bb.w);
        }
        for (int kk = 0; kk < 16; kk++) {
            float4 az = __ldg(z4 + kk);
            float av[4] = {az.x, az.y, az.z, az.w};
#pragma unroll
            for (int s = 0; s < 4; s++) {
                int k = kk * 4 + s;
                u64 pz = pack2s(av[s]);
#pragma unroll
                for (int jj = 0; jj < 16; jj++) {
                    ulonglong2 w = sW1[k * 16 + jj];
                    ffma2(acc[2 * jj], pz, w.x);
                    ffma2(acc[2 * jj + 1], pz, w.y);
                }
            }
        }
        {
            float4* tstage = reinterpret_cast<float4*>(g_nb + nn * D);
#pragma unroll
            for (int jj = 0; jj < 16; jj++) {
                float2 p0 = unpack2(acc[2 * jj]);
                float2 p1 = unpack2(acc[2 * jj + 1]);
                tstage[jj] = make_float4(fmaxf(p0.x, 0.f), fmaxf(p0.y, 0.f),
                                         fmaxf(p1.x, 0.f), fmaxf(p1.y, 0.f));
            }
        }
#pragma unroll
        for (int jj = 0; jj < 16; jj++) {
            float4 bb = __ldg(b2v + jj);
            acc[2 * jj] = pack2(bb.x, bb.y);
            acc[2 * jj + 1] = pack2(bb.z, bb.w);
        }
        const float4* t4 = reinterpret_cast<const float4*>(g_nb + nn * D);
        for (int kk = 0; kk < 16; kk++) {
            float4 at = t4[kk];
            float av[4] = {at.x, at.y, at.z, at.w};
#pragma unroll
            for (int s = 0; s < 4; s++) {
                int k = kk * 4 + s;
                u64 pt = pack2s(av[s]);
#pragma unroll
                for (int jj = 0; jj < 16; jj++) {
                    ulonglong2 w = sW2[k * 16 + jj];
                    ffma2(acc[2 * jj], pt, w.x);
                    ffma2(acc[2 * jj + 1], pt, w.y);
                }
            }
        }
        if (valid) {
            float4* o = reinterpret_cast<float4*>(g_h3 + n * D);
#pragma unroll
            for (int jj = 0; jj < 16; jj++) {
                float2 p0 = unpack2(acc[2 * jj]);
                float2 p1 = unpack2(acc[2 * jj + 1]);
                o[jj] = make_float4(fmaxf(p0.x, 0.f), fmaxf(p0.y, 0.f),
                                    fmaxf(p1.x, 0.f), fmaxf(p1.y, 0.f));
            }
        }
    }
}

// ---------------- fused pool+final: warp per graph; batch is SORTED ----------------
__global__ void __launch_bounds__(128) k_final2(const int* __restrict__ batch,
                                                const float* __restrict__ Wp1,
                                                const float* __restrict__ Wp2,
                                                const float* __restrict__ Wp3,
                                                float* __restrict__ out, int Gn, int n_nodes) {
    __shared__ float s1[D * D];
    __shared__ float s2[D * D];
    __shared__ float s3[D * D];
    for (int i = threadIdx.x; i < D * D; i += blockDim.x) { s1[i] = Wp1[i]; s2[i] = Wp2[i]; s3[i] = Wp3[i]; }
    __syncthreads();
    int warp = threadIdx.x >> 5, lane = threadIdx.x & 31;
    int g = blockIdx.x * 4 + warp;
    if (g >= Gn) return;
    int lo = 0, hi = n_nodes;
    while (lo < hi) { int mid = (lo + hi) >> 1; if (__ldg(&batch[mid]) < g) lo = mid + 1; else hi = mid; }
    int start = lo;
    hi = n_nodes;
    while (lo < hi) { int mid = (lo + hi) >> 1; if (__ldg(&batch[mid]) < g + 1) lo = mid + 1; else hi = mid; }
    int end = lo;
    float ic = 1.0f / fmaxf((float)(end - start), 1.0f);
    float a0 = 0.f, a1 = 0.f, b0 = 0.f, b1 = 0.f, c0 = 0.f, c1 = 0.f;
    float a0b = 0.f, a1b = 0.f, b0b = 0.f, b1b = 0.f, c0b = 0.f, c1b = 0.f;
    int nn = start;
    for (; nn + 2 <= end; nn += 2) {
        a0 += g_h1[nn * D + lane];  a1 += g_h1[nn * D + lane + 32];
        b0 += g_h2[nn * D + lane];  b1 += g_h2[nn * D + lane + 32];
        c0 += g_h3[nn * D + lane];  c1 += g_h3[nn * D + lane + 32];
        a0b += g_h1[(nn + 1) * D + lane];  a1b += g_h1[(nn + 1) * D + lane + 32];
        b0b += g_h2[(nn + 1) * D + lane];  b1b += g_h2[(nn + 1) * D + lane + 32];
        c0b += g_h3[(nn + 1) * D + lane];  c1b += g_h3[(nn + 1) * D + lane + 32];
    }
    for (; nn < end; nn++) {
        a0 += g_h1[nn * D + lane];  a1 += g_h1[nn * D + lane + 32];
        b0 += g_h2[nn * D + lane];  b1 += g_h2[nn * D + lane + 32];
        c0 += g_h3[nn * D + lane];  c1 += g_h3[nn * D + lane + 32];
    }
    a0 = (a0 + a0b) * ic; a1 = (a1 + a1b) * ic;
    b0 = (b0 + b0b) * ic; b1 = (b1 + b1b) * ic;
    c0 = (c0 + c0b) * ic; c1 = (c1 + c1b) * ic;
    float acc0 = 0.f, acc1 = 0.f;
#pragma unroll
    for (int k = 0; k < 32; k++) {
        float va = __shfl_sync(0xffffffffu, a0, k);
        float vb = __shfl_sync(0xffffffffu, b0, k);
        float vc = __shfl_sync(0xffffffffu, c0, k);
        acc0 += va * s1[k * D + lane] + vb * s2[k * D + lane] + vc * s3[k * D + lane];
        acc1 += va * s1[k * D + lane + 32] + vb * s2[k * D + lane + 32] + vc * s3[k * D + lane + 32];
    }
#pragma unroll
    for (int k = 0; k < 32; k++) {
        float va = __shfl_sync(0xffffffffu, a1, k);
        float vb = __shfl_sync(0xffffffffu, b1, k);
        float vc = __shfl_sync(0xffffffffu, c1, k);
        acc0 += va * s1[(k + 32) * D + lane] + vb * s2[(k + 32) * D + lane] + vc * s3[(k + 32) * D + lane];
        acc1 += va * s1[(k + 32) * D + lane + 32] + vb * s2[(k + 32) * D + lane + 32] + vc * s3[(k + 32) * D + lane + 32];
    }
    out[g * D + lane] = fmaxf(acc0, 0.f);
    out[g * D + lane + 32] = fmaxf(acc1, 0.f);
}

// ---------------- launch ----------------
extern "C" void kernel_launch(void* const* d_in, const int* in_sizes, int n_in,
                              void* d_out, int out_size) {
    const int* x      = (const int*)d_in[0];
    const int* ei     = (const int*)d_in[1];
    const int* batch  = (const int*)d_in[2];
    const float* emb  = (const float*)d_in[3];
    const float* Wgcn = (const float*)d_in[4];
    const float* Wsl  = (const float*)d_in[5];
    const float* Wsr  = (const float*)d_in[6];
    const float* Wg1  = (const float*)d_in[7];
    const float* bg1  = (const float*)d_in[8];
    const float* Wg2  = (const float*)d_in[9];
    const float* bg2  = (const float*)d_in[10];
    const float* Wp1  = (const float*)d_in[11];
    const float* Wp2  = (const float*)d_in[12];
    const float* Wp3  = (const float*)d_in[13];
    float* out = (float*)d_out;

    int n = in_sizes[0];
    int e = in_sizes[1] / 2;
    int v = in_sizes[3] / D;
    int g = out_size / D;

    int preblk = (e / 8 + 255) / 256;
    k_pre<<<preblk, 256>>>(ei, emb, Wgcn, v, e);
    k_scan<<<1, 1024>>>(n);
    k_scatter<<<(e / 8 + 255) / 256, 256>>>(ei, x, e);

    int gth = n * 16;
    int gblk = (gth + 255) / 256;
    k_gather_gcn<<<gblk, 256>>>(n);
    k_gather_mean<<<gblk, 256>>>(n);

    int ntiles = (n + 31) / 32;
    int ggrid = (ntiles + 7) / 8;
    k_sage<<<ggrid, 256>>>(Wsl, Wsr, n);
    k_gather_gin<<<gblk, 256>>>(n);
    k_gin<<<ggrid, 256>>>(Wg1, bg1, Wg2, bg2, n);
    k_final2<<<(g + 3) / 4, 128>>>(batch, Wp1, Wp2, Wp3, out, g, n);
}

// round 16
// speedup vs baseline: 1.4338x; 1.4338x over previous
#include <cuda_runtime.h>

#define D 64
#define MAXN 50000
#define MAXE 800000
#define MAXG 512
#define MAXV 128

typedef unsigned long long u64;

// ---------------- scratch (device globals; no allocation) ----------------
__device__ __align__(128) float g_embW[MAXV * D];
__device__ __align__(128) float g_h1[MAXN * D];
__device__ __align__(128) float g_nb[MAXN * D];   // SAGE mean; later GIN t-stage scratch
__device__ __align__(128) float g_h2[MAXN * D];
__device__ __align__(128) float g_z[MAXN * D];
__device__ __align__(128) float g_h3[MAXN * D];
// CSR build
__device__ __align__(128) int g_deg[MAXN];     // zeroed by k_scan after use
__device__ __align__(128) int g_off[MAXN + 8];
__device__ __align__(128) int g_cursor[MAXN];
__device__ __align__(128) int2 g_sx[MAXE];     // {src, x[src]} per CSR slot

__device__ __forceinline__ float4 f4add(float4 a, float4 b) {
    return make_float4(a.x + b.x, a.y + b.y, a.z + b.z, a.w + b.w);
}

// packed f32x2 helpers (Blackwell)
__device__ __forceinline__ u64 pack2s(float x) {
    u64 r; asm("mov.b64 %0, {%1,%1};" : "=l"(r) : "f"(x)); return r;
}
__device__ __forceinline__ u64 pack2(float x, float y) {
    u64 r; asm("mov.b64 %0, {%1,%2};" : "=l"(r) : "f"(x), "f"(y)); return r;
}
__device__ __forceinline__ void ffma2(u64& d, u64 a, u64 b) {
    asm("fma.rn.f32x2 %0, %1, %2, %3;" : "=l"(d) : "l"(a), "l"(b), "l"(d));
}
__device__ __forceinline__ float2 unpack2(u64 v) {
    float2 f; asm("mov.b64 {%0,%1}, %2;" : "=f"(f.x), "=f"(f.y) : "l"(v)); return f;
}

// ---------------- pre: embW = emb@W + degree histogram (8 edges/thread) ----------------
__global__ void k_pre(const int* __restrict__ ei, const float* __restrict__ emb,
                      const float* __restrict__ W, int Vn, int E_) {
    int gid = blockIdx.x * blockDim.x + threadIdx.x;
    int stride = gridDim.x * blockDim.x;
    for (int idx = gid; idx < Vn * D; idx += stride) {
        int v = idx >> 6, j = idx & 63;
        float s = 0.f;
#pragma unroll
        for (int k = 0; k < D; k++) s += emb[v * D + k] * W[k * D + j];
        g_embW[idx] = s;
    }
    if ((E_ & 3) == 0) {
        for (int base = gid * 8; base < E_; base += stride * 8) {
            if (base + 7 < E_) {
                int4 d0 = *reinterpret_cast<const int4*>(ei + E_ + base);
                int4 d1 = *reinterpret_cast<const int4*>(ei + E_ + base + 4);
                atomicAdd(&g_deg[d0.x], 1);
                atomicAdd(&g_deg[d0.y], 1);
                atomicAdd(&g_deg[d0.z], 1);
                atomicAdd(&g_deg[d0.w], 1);
                atomicAdd(&g_deg[d1.x], 1);
                atomicAdd(&g_deg[d1.y], 1);
                atomicAdd(&g_deg[d1.z], 1);
                atomicAdd(&g_deg[d1.w], 1);
            } else {
#pragma unroll
                for (int u = 0; u < 8; u++) {
                    int e = base + u;
                    if (e < E_) atomicAdd(&g_deg[__ldg(&ei[E_ + e])], 1);
                }
            }
        }
    } else {
        for (int base = gid * 8; base < E_; base += stride * 8) {
#pragma unroll
            for (int u = 0; u < 8; u++) {
                int e = base + u;
                if (e < E_) atomicAdd(&g_deg[__ldg(&ei[E_ + e])], 1);
            }
        }
    }
}

// ---------------- single-block exclusive scan (8 elems/thread, 8192/iter) ----------------
__global__ void __launch_bounds__(1024) k_scan(int n) {
    __shared__ int wsum[32];
    __shared__ int s_total;
    int tid = threadIdx.x, lane = tid & 31, warp = tid >> 5;
    int carry = 0;
    for (int base = 0; base < n; base += 8192) {
        int i8 = base + tid * 8;
        int va[8];
#pragma unroll
        for (int u = 0; u < 8; u++) va[u] = 0;
        if (i8 + 7 < n) {
            int4 lo = *reinterpret_cast<const int4*>(g_deg + i8);
            int4 hi = *reinterpret_cast<const int4*>(g_deg + i8 + 4);
            va[0] = lo.x; va[1] = lo.y; va[2] = lo.z; va[3] = lo.w;
            va[4] = hi.x; va[5] = hi.y; va[6] = hi.z; va[7] = hi.w;
        } else if (i8 < n) {
#pragma unroll
            for (int u = 0; u < 8; u++)
                if (i8 + u < n) va[u] = g_deg[i8 + u];
        }
        int sum = 0;
#pragma unroll
        for (int u = 0; u < 8; u++) sum += va[u];
        int inc = sum;
#pragma unroll
        for (int off = 1; off < 32; off <<= 1) {
            int tv = __shfl_up_sync(0xffffffffu, inc, off);
            if (lane >= off) inc += tv;
        }
        if (lane == 31) wsum[warp] = inc;
        __syncthreads();
        if (warp == 0) {
            int w = wsum[lane];
            int wi = w;
#pragma unroll
            for (int off = 1; off < 32; off <<= 1) {
                int tv = __shfl_up_sync(0xffffffffu, wi, off);
                if (lane >= off) wi += tv;
            }
            wsum[lane] = wi - w;
            if (lane == 31) s_total = wi;
        }
        __syncthreads();
        int o[8];
        o[0] = carry + inc - sum + wsum[warp];
#pragma unroll
        for (int u = 1; u < 8; u++) o[u] = o[u - 1] + va[u - 1];
        if (i8 + 7 < n) {
            *reinterpret_cast<int4*>(g_off + i8) = make_int4(o[0], o[1], o[2], o[3]);
            *reinterpret_cast<int4*>(g_off + i8 + 4) = make_int4(o[4], o[5], o[6], o[7]);
            *reinterpret_cast<int4*>(g_cursor + i8) = make_int4(o[0], o[1], o[2], o[3]);
            *reinterpret_cast<int4*>(g_cursor + i8 + 4) = make_int4(o[4], o[5], o[6], o[7]);
            *reinterpret_cast<int4*>(g_deg + i8) = make_int4(0, 0, 0, 0);
            *reinterpret_cast<int4*>(g_deg + i8 + 4) = make_int4(0, 0, 0, 0);
        } else if (i8 < n) {
#pragma unroll
            for (int u = 0; u < 8; u++) {
                if (i8 + u < n) { g_off[i8 + u] = o[u]; g_cursor[i8 + u] = o[u]; g_deg[i8 + u] = 0; }
            }
        }
        carry += s_total;
        __syncthreads();
    }
    if (tid == 0) g_off[n] = carry;
}

// ---------------- scatter: interleaved CSR {src, x[src]} (8 edges/thread) ----------------
__global__ void k_scatter(const int* __restrict__ ei, const int* __restrict__ x, int E_) {
    int e0 = (blockIdx.x * blockDim.x + threadIdx.x) * 8;
    if ((E_ & 3) == 0 && e0 + 7 < E_) {
        int4 s0 = *reinterpret_cast<const int4*>(ei + e0);
        int4 s1 = *reinterpret_cast<const int4*>(ei + e0 + 4);
        int4 d0 = *reinterpret_cast<const int4*>(ei + E_ + e0);
        int4 d1 = *reinterpret_cast<const int4*>(ei + E_ + e0 + 4);
        int x0 = __ldg(&x[s0.x]);
        int x1 = __ldg(&x[s0.y]);
        int x2 = __ldg(&x[s0.z]);
        int x3 = __ldg(&x[s0.w]);
        int x4 = __ldg(&x[s1.x]);
        int x5 = __ldg(&x[s1.y]);
        int x6 = __ldg(&x[s1.z]);
        int x7 = __ldg(&x[s1.w]);
        int p0 = atomicAdd(&g_cursor[d0.x], 1);
        int p1 = atomicAdd(&g_cursor[d0.y], 1);
        int p2 = atomicAdd(&g_cursor[d0.z], 1);
        int p3 = atomicAdd(&g_cursor[d0.w], 1);
        int p4 = atomicAdd(&g_cursor[d1.x], 1);
        int p5 = atomicAdd(&g_cursor[d1.y], 1);
        int p6 = atomicAdd(&g_cursor[d1.z], 1);
        int p7 = atomicAdd(&g_cursor[d1.w], 1);
        g_sx[p0] = make_int2(s0.x, x0);
        g_sx[p1] = make_int2(s0.y, x1);
        g_sx[p2] = make_int2(s0.z, x2);
        g_sx[p3] = make_int2(s0.w, x3);
        g_sx[p4] = make_int2(s1.x, x4);
        g_sx[p5] = make_int2(s1.y, x5);
        g_sx[p6] = make_int2(s1.z, x6);
        g_sx[p7] = make_int2(s1.w, x7);
    } else {
#pragma unroll
        for (int u = 0; u < 8; u++) {
            int e = e0 + u;
            if (e < E_) {
                int src = __ldg(&ei[e]);
                int dst = __ldg(&ei[E_ + e]);
                int xv = __ldg(&x[src]);
                int pos = atomicAdd(&g_cursor[dst], 1);
                g_sx[pos] = make_int2(src, xv);
            }
        }
    }
}

// ---------------- GCN gather: h1[n] = relu(sum_nb embW[x[src]]) ----------------
__global__ void k_gather_gcn(int n_nodes) {
    int gid = blockIdx.x * blockDim.x + threadIdx.x;
    int node = gid >> 4, q = gid & 15;
    if (node >= n_nodes) return;
    int start = g_off[node];
    int cnt = g_off[node + 1] - start;
    const float4* embW4 = reinterpret_cast<const float4*>(g_embW);
    float4 acc = make_float4(0.f, 0.f, 0.f, 0.f);
    int t = 0;
    for (; t + 4 <= cnt; t += 4) {
        int2 i0 = __ldg(&g_sx[start + t + 0]);
        int2 i1 = __ldg(&g_sx[start + t + 1]);
        int2 i2 = __ldg(&g_sx[start + t + 2]);
        int2 i3 = __ldg(&g_sx[start + t + 3]);
        float4 v0 = embW4[i0.y * 16 + q];
        float4 v1 = embW4[i1.y * 16 + q];
        float4 v2 = embW4[i2.y * 16 + q];
        float4 v3 = embW4[i3.y * 16 + q];
        acc = f4add(acc, f4add(f4add(v0, v1), f4add(v2, v3)));
    }
    for (; t < cnt; t++) {
        int2 i0 = __ldg(&g_sx[start + t]);
        acc = f4add(acc, embW4[i0.y * 16 + q]);
    }
    acc.x = fmaxf(acc.x, 0.f); acc.y = fmaxf(acc.y, 0.f);
    acc.z = fmaxf(acc.z, 0.f); acc.w = fmaxf(acc.w, 0.f);
    reinterpret_cast<float4*>(g_h1 + node * D)[q] = acc;
}

// ---------------- SAGE gather: nb[n] = mean_nb h1[src] ----------------
__global__ void k_gather_mean(int n_nodes) {
    int gid = blockIdx.x * blockDim.x + threadIdx.x;
    int node = gid >> 4, q = gid & 15;
    if (node >= n_nodes) return;
    int start = g_off[node];
    int cnt = g_off[node + 1] - start;
    float4 acc = make_float4(0.f, 0.f, 0.f, 0.f);
    int t = 0;
    for (; t + 4 <= cnt; t += 4) {
        int2 i0 = __ldg(&g_sx[start + t + 0]);
        int2 i1 = __ldg(&g_sx[start + t + 1]);
        int2 i2 = __ldg(&g_sx[start + t + 2]);
        int2 i3 = __ldg(&g_sx[start + t + 3]);
        float4 v0 = reinterpret_cast<const float4*>(g_h1 + i0.x * D)[q];
        float4 v1 = reinterpret_cast<const float4*>(g_h1 + i1.x * D)[q];
        float4 v2 = reinterpret_cast<const float4*>(g_h1 + i2.x * D)[q];
        float4 v3 = reinterpret_cast<const float4*>(g_h1 + i3.x * D)[q];
        acc = f4add(acc, f4add(f4add(v0, v1), f4add(v2, v3)));
    }
    for (; t < cnt; t++) {
        int2 i0 = __ldg(&g_sx[start + t]);
        acc = f4add(acc, reinterpret_cast<const float4*>(g_h1 + i0.x * D)[q]);
    }
    float invd = 1.0f / fmaxf((float)cnt, 1.0f);
    acc.x *= invd; acc.y *= invd; acc.z *= invd; acc.w *= invd;
    reinterpret_cast<float4*>(g_nb + node * D)[q] = acc;
}

// ---------------- GIN gather: z[n] = h2[n] + sum_nb h2[src] ----------------
__global__ void k_gather_gin(int n_nodes) {
    int gid = blockIdx.x * blockDim.x + threadIdx.x;
    int node = gid >> 4, q = gid & 15;
    if (node >= n_nodes) return;
    int start = g_off[node];
    int cnt = g_off[node + 1] - start;
    float4 acc = reinterpret_cast<const float4*>(g_h2 + node * D)[q];
    int t = 0;
    for (; t + 4 <= cnt; t += 4) {
        int2 i0 = __ldg(&g_sx[start + t + 0]);
        int2 i1 = __ldg(&g_sx[start + t + 1]);
        int2 i2 = __ldg(&g_sx[start + t + 2]);
        int2 i3 = __ldg(&g_sx[start + t + 3]);
        float4 v0 = reinterpret_cast<const float4*>(g_h2 + i0.x * D)[q];
        float4 v1 = reinterpret_cast<const float4*>(g_h2 + i1.x * D)[q];
        float4 v2 = reinterpret_cast<const float4*>(g_h2 + i2.x * D)[q];
        float4 v3 = reinterpret_cast<const float4*>(g_h2 + i3.x * D)[q];
        acc = f4add(acc, f4add(f4add(v0, v1), f4add(v2, v3)));
    }
    for (; t < cnt; t++) {
        int2 i0 = __ldg(&g_sx[start + t]);
        acc = f4add(acc, reinterpret_cast<const float4*>(g_h2 + i0.x * D)[q]);
    }
    reinterpret_cast<float4*>(g_z + node * D)[q] = acc;
}

// ---------------- SAGE GEMM: h2 = relu(nb @ Wl + h1 @ Wr) ----------------
__global__ void __launch_bounds__(256) k_sage(const float* __restrict__ Wl,
                                              const float* __restrict__ Wr, int n_nodes) {
    __shared__ ulonglong2 sWl[D * 16];
    __shared__ ulonglong2 sWr[D * 16];
    {
        const ulonglong2* wl2 = reinterpret_cast<const ulonglong2*>(Wl);
        const ulonglong2* wr2 = reinterpret_cast<const ulonglong2*>(Wr);
        for (int i = threadIdx.x; i < D * 16; i += blockDim.x) { sWl[i] = wl2[i]; sWr[i] = wr2[i]; }
    }
    __syncthreads();
    int lane = threadIdx.x & 31, warp = threadIdx.x >> 5;
    int ntiles = (n_nodes + 31) / 32;
    int nwarps = gridDim.x * 8;
    for (int tile = blockIdx.x * 8 + warp; tile < ntiles; tile += nwarps) {
        int n = tile * 32 + lane;
        bool valid = n < n_nodes;
        int nn = valid ? n : (n_nodes - 1);
        const float4* nb4 = reinterpret_cast<const float4*>(g_nb + nn * D);
        const float4* h4 = reinterpret_cast<const float4*>(g_h1 + nn * D);
        u64 acc[32];
#pragma unroll
        for (int j = 0; j < 32; j++) acc[j] = 0ULL;
        for (int kk = 0; kk < 16; kk++) {
            float4 anb = __ldg(nb4 + kk);
            float4 ah = __ldg(h4 + kk);
            float an[4] = {anb.x, anb.y, anb.z, anb.w};
            float av[4] = {ah.x, ah.y, ah.z, ah.w};
#pragma unroll
            for (int s = 0; s < 4; s++) {
                int k = kk * 4 + s;
                u64 pa = pack2s(an[s]);
                u64 ph = pack2s(av[s]);
#pragma unroll
                for (int jj = 0; jj < 16; jj++) {
                    ulonglong2 wl = sWl[k * 16 + jj];
                    ulonglong2 wr = sWr[k * 16 + jj];
                    ffma2(acc[2 * jj], pa, wl.x);
                    ffma2(acc[2 * jj], ph, wr.x);
                    ffma2(acc[2 * jj + 1], pa, wl.y);
                    ffma2(acc[2 * jj + 1], ph, wr.y);
                }
            }
        }
        if (valid) {
            float4* o = reinterpret_cast<float4*>(g_h2 + n * D);
#pragma unroll
            for (int jj = 0; jj < 16; jj++) {
                float2 p0 = unpack2(acc[2 * jj]);
                float2 p1 = unpack2(acc[2 * jj + 1]);
                o[jj] = make_float4(fmaxf(p0.x, 0.f), fmaxf(p0.y, 0.f),
                                    fmaxf(p1.x, 0.f), fmaxf(p1.y, 0.f));
            }
        }
    }
}

// ---------------- GIN GEMM: h3 = relu(relu(z@W1+b1)@W2+b2) ----------------
__global__ void __launch_bounds__(256) k_gin(const float* __restrict__ W1,
                                             const float* __restrict__ b1,
                                             const float* __restrict__ W2,
                                             const float* __restrict__ b2, int n_nodes) {
    __shared__ ulonglong2 sW1[D * 16];
    __shared__ ulonglong2 sW2[D * 16];
    {
        const ulonglong2* w12 = reinterpret_cast<const ulonglong2*>(W1);
        const ulonglong2* w22 = reinterpret_cast<const ulonglong2*>(W2);
        for (int i = threadIdx.x; i < D * 16; i += blockDim.x) { sW1[i] = w12[i]; sW2[i] = w22[i]; }
    }
    __syncthreads();
    int lane = threadIdx.x & 31, warp = threadIdx.x >> 5;
    int ntiles = (n_nodes + 31) / 32;
    int nwarps = gridDim.x * 8;
    const float4* b1v = reinterpret_cast<const float4*>(b1);
    const float4* b2v = reinterpret_cast<const float4*>(b2);
    for (int tile = blockIdx.x * 8 + warp; tile < ntiles; tile += nwarps) {
        int n = tile * 32 + lane;
        bool valid = n < n_nodes;
        int nn = valid ? n : (n_nodes - 1);
        const float4* z4 = reinterpret_cast<const float4*>(g_z + nn * D);
        u64 acc[32];
#pragma unroll
        for (int jj = 0; jj < 16; jj++) {
            float4 bb = __ldg(b1v + jj);
            acc[2 * jj] = pack2(bb.x, bb.y);
            acc[2 * jj + 1] = pack2(bb.z, bb.w);
        }
        for (int kk = 0; kk < 16; kk++) {
            float4 az = __ldg(z4 + kk);
            float av[4] = {az.x, az.y, az.z, az.w};
#pragma unroll
            for (int s = 0; s < 4; s++) {
                int k = kk * 4 + s;
                u64 pz = pack2s(av[s]);
#pragma unroll
                for (int jj = 0; jj < 16; jj++) {
                    ulonglong2 w = sW1[k * 16 + jj];
                    ffma2(acc[2 * jj], pz, w.x);
                    ffma2(acc[2 * jj + 1], pz, w.y);
                }
            }
        }
        {
            float4* tstage = reinterpret_cast<float4*>(g_nb + nn * D);
#pragma unroll
            for (int jj = 0; jj < 16; jj++) {
                float2 p0 = unpack2(acc[2 * jj]);
                float2 p1 = unpack2(acc[2 * jj + 1]);
                tstage[jj] = make_float4(fmaxf(p0.x, 0.f), fmaxf(p0.y, 0.f),
                                         fmaxf(p1.x, 0.f), fmaxf(p1.y, 0.f));
            }
        }
#pragma unroll
        for (int jj = 0; jj < 16; jj++) {
            float4 bb = __ldg(b2v + jj);
            acc[2 * jj] = pack2(bb.x, bb.y);
            acc[2 * jj + 1] = pack2(bb.z, bb.w);
        }
        const float4* t4 = reinterpret_cast<const float4*>(g_nb + nn * D);
        for (int kk = 0; kk < 16; kk++) {
            float4 at = t4[kk];
            float av[4] = {at.x, at.y, at.z, at.w};
#pragma unroll
            for (int s = 0; s < 4; s++) {
                int k = kk * 4 + s;
                u64 pt = pack2s(av[s]);
#pragma unroll
                for (int jj = 0; jj < 16; jj++) {
                    ulonglong2 w = sW2[k * 16 + jj];
                    ffma2(acc[2 * jj], pt, w.x);
                    ffma2(acc[2 * jj + 1], pt, w.y);
                }
            }
        }
        if (valid) {
            float4* o = reinterpret_cast<float4*>(g_h3 + n * D);
#pragma unroll
            for (int jj = 0; jj < 16; jj++) {
                float2 p0 = unpack2(acc[2 * jj]);
                float2 p1 = unpack2(acc[2 * jj + 1]);
                o[jj] = make_float4(fmaxf(p0.x, 0.f), fmaxf(p0.y, 0.f),
                                    fmaxf(p1.x, 0.f), fmaxf(p1.y, 0.f));
            }
        }
    }
}

// ---------------- fused pool+final: warp per graph; batch is SORTED ----------------
__global__ void __launch_bounds__(128) k_final2(const int* __restrict__ batch,
                                                const float* __restrict__ Wp1,
                                                const float* __restrict__ Wp2,
                                                const float* __restrict__ Wp3,
                                                float* __restrict__ out, int Gn, int n_nodes) {
    __shared__ float s1[D * D];
    __shared__ float s2[D * D];
    __shared__ float s3[D * D];
    for (int i = threadIdx.x; i < D * D; i += blockDim.x) { s1[i] = Wp1[i]; s2[i] = Wp2[i]; s3[i] = Wp3[i]; }
    __syncthreads();
    int warp = threadIdx.x >> 5, lane = threadIdx.x & 31;
    int g = blockIdx.x * 4 + warp;
    if (g >= Gn) return;
    int lo = 0, hi = n_nodes;
    while (lo < hi) { int mid = (lo + hi) >> 1; if (__ldg(&batch[mid]) < g) lo = mid + 1; else hi = mid; }
    int start = lo;
    hi = n_nodes;
    while (lo < hi) { int mid = (lo + hi) >> 1; if (__ldg(&batch[mid]) < g + 1) lo = mid + 1; else hi = mid; }
    int end = lo;
    float ic = 1.0f / fmaxf((float)(end - start), 1.0f);
    float a0 = 0.f, a1 = 0.f, b0 = 0.f, b1 = 0.f, c0 = 0.f, c1 = 0.f;
    float a0b = 0.f, a1b = 0.f, b0b = 0.f, b1b = 0.f, c0b = 0.f, c1b = 0.f;
    int nn = start;
    for (; nn + 2 <= end; nn += 2) {
        a0 += g_h1[nn * D + lane];  a1 += g_h1[nn * D + lane + 32];
        b0 += g_h2[nn * D + lane];  b1 += g_h2[nn * D + lane + 32];
        c0 += g_h3[nn * D + lane];  c1 += g_h3[nn * D + lane + 32];
        a0b += g_h1[(nn + 1) * D + lane];  a1b += g_h1[(nn + 1) * D + lane + 32];
        b0b += g_h2[(nn + 1) * D + lane];  b1b += g_h2[(nn + 1) * D + lane + 32];
        c0b += g_h3[(nn + 1) * D + lane];  c1b += g_h3[(nn + 1) * D + lane + 32];
    }
    for (; nn < end; nn++) {
        a0 += g_h1[nn * D + lane];  a1 += g_h1[nn * D + lane + 32];
        b0 += g_h2[nn * D + lane];  b1 += g_h2[nn * D + lane + 32];
        c0 += g_h3[nn * D + lane];  c1 += g_h3[nn * D + lane + 32];
    }
    a0 = (a0 + a0b) * ic; a1 = (a1 + a1b) * ic;
    b0 = (b0 + b0b) * ic; b1 = (b1 + b1b) * ic;
    c0 = (c0 + c0b) * ic; c1 = (c1 + c1b) * ic;
    float acc0 = 0.f, acc1 = 0.f;
#pragma unroll
    for (int k = 0; k < 32; k++) {
        float va = __shfl_sync(0xffffffffu, a0, k);
        float vb = __shfl_sync(0xffffffffu, b0, k);
        float vc = __shfl_sync(0xffffffffu, c0, k);
        acc0 += va * s1[k * D + lane] + vb * s2[k * D + lane] + vc * s3[k * D + lane];
        acc1 += va * s1[k * D + lane + 32] + vb * s2[k * D + lane + 32] + vc * s3[k * D + lane + 32];
    }
#pragma unroll
    for (int k = 0; k < 32; k++) {
        float va = __shfl_sync(0xffffffffu, a1, k);
        float vb = __shfl_sync(0xffffffffu, b1, k);
        float vc = __shfl_sync(0xffffffffu, c1, k);
        acc0 += va * s1[(k + 32) * D + lane] + vb * s2[(k + 32) * D + lane] + vc * s3[(k + 32) * D + lane];
        acc1 += va * s1[(k + 32) * D + lane + 32] + vb * s2[(k + 32) * D + lane + 32] + vc * s3[(k + 32) * D + lane + 32];
    }
    out[g * D + lane] = fmaxf(acc0, 0.f);
    out[g * D + lane + 32] = fmaxf(acc1, 0.f);
}

// ---------------- launch ----------------
extern "C" void kernel_launch(void* const* d_in, const int* in_sizes, int n_in,
                              void* d_out, int out_size) {
    const int* x      = (const int*)d_in[0];
    const int* ei     = (const int*)d_in[1];
    const int* batch  = (const int*)d_in[2];
    const float* emb  = (const float*)d_in[3];
    const float* Wgcn = (const float*)d_in[4];
    const float* Wsl  = (const float*)d_in[5];
    const float* Wsr  = (const float*)d_in[6];
    const float* Wg1  = (const float*)d_in[7];
    const float* bg1  = (const float*)d_in[8];
    const float* Wg2  = (const float*)d_in[9];
    const float* bg2  = (const float*)d_in[10];
    const float* Wp1  = (const float*)d_in[11];
    const float* Wp2  = (const float*)d_in[12];
    const float* Wp3  = (const float*)d_in[13];
    float* out = (float*)d_out;

    int n = in_sizes[0];
    int e = in_sizes[1] / 2;
    int v = in_sizes[3] / D;
    int g = out_size / D;

    int preblk = (e / 8 + 255) / 256;
    k_pre<<<preblk, 256>>>(ei, emb, Wgcn, v, e);
    k_scan<<<1, 1024>>>(n);
    k_scatter<<<(e / 8 + 255) / 256, 256>>>(ei, x, e);

    int gth = n * 16;
    int gblk = (gth + 255) / 256;
    k_gather_gcn<<<gblk, 256>>>(n);
    k_gather_mean<<<gblk, 256>>>(n);

    int ntiles = (n + 31) / 32;
    int ggrid = (ntiles + 7) / 8;
    k_sage<<<ggrid, 256>>>(Wsl, Wsr, n);
    k_gather_gin<<<gblk, 256>>>(n);
    k_gin<<<ggrid, 256>>>(Wg1, bg1, Wg2, bg2, n);
    k_final2<<<(g + 3) / 4, 128>>>(batch, Wp1, Wp2, Wp3, out, g, n);
}

// round 17
// speedup vs baseline: 1.4945x; 1.0424x over previous
#include <cuda_runtime.h>

#define D 64
#define MAXN 50000
#define MAXE 800000
#define MAXG 512
#define MAXV 128

typedef unsigned long long u64;

// ---------------- scratch (device globals; no allocation) ----------------
__device__ __align__(128) float g_embW[MAXV * D];
__device__ __align__(128) float g_h1[MAXN * D];
__device__ __align__(128) float g_nb[MAXN * D];   // SAGE mean; later GIN t-stage scratch
__device__ __align__(128) float g_h2[MAXN * D];
__device__ __align__(128) float g_z[MAXN * D];
__device__ __align__(128) float g_h3[MAXN * D];
// CSR build
__device__ __align__(128) int g_deg[MAXN];     // zeroed by k_scan after use
__device__ __align__(128) int g_off[MAXN + 4];
__device__ __align__(128) int g_cursor[MAXN];
__device__ __align__(128) int2 g_sx[MAXE];     // {src, x[src]} per CSR slot

__device__ __forceinline__ float4 f4add(float4 a, float4 b) {
    return make_float4(a.x + b.x, a.y + b.y, a.z + b.z, a.w + b.w);
}

// packed f32x2 helpers (Blackwell)
__device__ __forceinline__ u64 pack2s(float x) {
    u64 r; asm("mov.b64 %0, {%1,%1};" : "=l"(r) : "f"(x)); return r;
}
__device__ __forceinline__ u64 pack2(float x, float y) {
    u64 r; asm("mov.b64 %0, {%1,%2};" : "=l"(r) : "f"(x), "f"(y)); return r;
}
__device__ __forceinline__ void ffma2(u64& d, u64 a, u64 b) {
    asm("fma.rn.f32x2 %0, %1, %2, %3;" : "=l"(d) : "l"(a), "l"(b), "l"(d));
}
__device__ __forceinline__ float2 unpack2(u64 v) {
    float2 f; asm("mov.b64 {%0,%1}, %2;" : "=f"(f.x), "=f"(f.y) : "l"(v)); return f;
}

// ---------------- pre: embW = emb@W + degree histogram (8 edges/thread) ----------------
__global__ void k_pre(const int* __restrict__ ei, const float* __restrict__ emb,
                      const float* __restrict__ W, int Vn, int E_) {
    int gid = blockIdx.x * blockDim.x + threadIdx.x;
    int stride = gridDim.x * blockDim.x;
    for (int idx = gid; idx < Vn * D; idx += stride) {
        int v = idx >> 6, j = idx & 63;
        float s = 0.f;
#pragma unroll
        for (int k = 0; k < D; k++) s += emb[v * D + k] * W[k * D + j];
        g_embW[idx] = s;
    }
    if ((E_ & 3) == 0) {
        for (int base = gid * 8; base < E_; base += stride * 8) {
            if (base + 7 < E_) {
                int4 d0 = *reinterpret_cast<const int4*>(ei + E_ + base);
                int4 d1 = *reinterpret_cast<const int4*>(ei + E_ + base + 4);
                atomicAdd(&g_deg[d0.x], 1);
                atomicAdd(&g_deg[d0.y], 1);
                atomicAdd(&g_deg[d0.z], 1);
                atomicAdd(&g_deg[d0.w], 1);
                atomicAdd(&g_deg[d1.x], 1);
                atomicAdd(&g_deg[d1.y], 1);
                atomicAdd(&g_deg[d1.z], 1);
                atomicAdd(&g_deg[d1.w], 1);
            } else {
#pragma unroll
                for (int u = 0; u < 8; u++) {
                    int e = base + u;
                    if (e < E_) atomicAdd(&g_deg[__ldg(&ei[E_ + e])], 1);
                }
            }
        }
    } else {
        for (int base = gid * 8; base < E_; base += stride * 8) {
#pragma unroll
            for (int u = 0; u < 8; u++) {
                int e = base + u;
                if (e < E_) atomicAdd(&g_deg[__ldg(&ei[E_ + e])], 1);
            }
        }
    }
}

// ---------------- single-block exclusive scan (int4, 4096/iter) ----------------
__global__ void __launch_bounds__(1024) k_scan(int n) {
    __shared__ int wsum[32];
    __shared__ int s_total;
    int tid = threadIdx.x, lane = tid & 31, warp = tid >> 5;
    int carry = 0;
    for (int base = 0; base < n; base += 4096) {
        int i4 = base + tid * 4;
        int4 v = make_int4(0, 0, 0, 0);
        if (i4 + 3 < n) {
            v = *reinterpret_cast<const int4*>(g_deg + i4);
        } else if (i4 < n) {
            v.x = g_deg[i4];
            if (i4 + 1 < n) v.y = g_deg[i4 + 1];
            if (i4 + 2 < n) v.z = g_deg[i4 + 2];
        }
        int sum = v.x + v.y + v.z + v.w;
        int inc = sum;
#pragma unroll
        for (int off = 1; off < 32; off <<= 1) {
            int tv = __shfl_up_sync(0xffffffffu, inc, off);
            if (lane >= off) inc += tv;
        }
        if (lane == 31) wsum[warp] = inc;
        __syncthreads();
        if (warp == 0) {
            int w = wsum[lane];
            int wi = w;
#pragma unroll
            for (int off = 1; off < 32; off <<= 1) {
                int tv = __shfl_up_sync(0xffffffffu, wi, off);
                if (lane >= off) wi += tv;
            }
            wsum[lane] = wi - w;
            if (lane == 31) s_total = wi;
        }
        __syncthreads();
        int b0 = carry + inc - sum + wsum[warp];
        int4 o;
        o.x = b0;
        o.y = b0 + v.x;
        o.z = b0 + v.x + v.y;
        o.w = b0 + v.x + v.y + v.z;
        if (i4 + 3 < n) {
            *reinterpret_cast<int4*>(g_off + i4) = o;
            *reinterpret_cast<int4*>(g_cursor + i4) = o;
            *reinterpret_cast<int4*>(g_deg + i4) = make_int4(0, 0, 0, 0);
        } else if (i4 < n) {
            int ov[4] = {o.x, o.y, o.z, o.w};
#pragma unroll
            for (int u = 0; u < 4; u++) {
                if (i4 + u < n) { g_off[i4 + u] = ov[u]; g_cursor[i4 + u] = ov[u]; g_deg[i4 + u] = 0; }
            }
        }
        carry += s_total;
        __syncthreads();
    }
    if (tid == 0) g_off[n] = carry;
}

// ---------------- scatter: fill interleaved CSR {src, x[src]} (int4 loads) ----------------
__global__ void k_scatter(const int* __restrict__ ei, const int* __restrict__ x, int E_) {
    int e0 = (blockIdx.x * blockDim.x + threadIdx.x) * 4;
    if ((E_ & 3) == 0 && e0 + 3 < E_) {
        int4 s = *reinterpret_cast<const int4*>(ei + e0);
        int4 dd = *reinterpret_cast<const int4*>(ei + E_ + e0);
        int x0 = __ldg(&x[s.x]);
        int x1 = __ldg(&x[s.y]);
        int x2 = __ldg(&x[s.z]);
        int x3 = __ldg(&x[s.w]);
        int p0 = atomicAdd(&g_cursor[dd.x], 1);
        int p1 = atomicAdd(&g_cursor[dd.y], 1);
        int p2 = atomicAdd(&g_cursor[dd.z], 1);
        int p3 = atomicAdd(&g_cursor[dd.w], 1);
        g_sx[p0] = make_int2(s.x, x0);
        g_sx[p1] = make_int2(s.y, x1);
        g_sx[p2] = make_int2(s.z, x2);
        g_sx[p3] = make_int2(s.w, x3);
    } else {
#pragma unroll
        for (int u = 0; u < 4; u++) {
            int e = e0 + u;
            if (e < E_) {
                int src = __ldg(&ei[e]);
                int dst = __ldg(&ei[E_ + e]);
                int xv = __ldg(&x[src]);
                int pos = atomicAdd(&g_cursor[dst], 1);
                g_sx[pos] = make_int2(src, xv);
            }
        }
    }
}

// ---------------- GCN gather: h1[n] = relu(sum_nb embW[x[src]]) (L1-bound) ----
__global__ void k_gather_gcn(int n_nodes) {
    int gid = blockIdx.x * blockDim.x + threadIdx.x;
    int node = gid >> 4, q = gid & 15;
    if (node >= n_nodes) return;
    int start = g_off[node];
    int cnt = g_off[node + 1] - start;
    const float4* embW4 = reinterpret_cast<const float4*>(g_embW);
    float4 acc = make_float4(0.f, 0.f, 0.f, 0.f);
    int t = 0;
    for (; t + 4 <= cnt; t += 4) {
        int2 i0 = __ldg(&g_sx[start + t + 0]);
        int2 i1 = __ldg(&g_sx[start + t + 1]);
        int2 i2 = __ldg(&g_sx[start + t + 2]);
        int2 i3 = __ldg(&g_sx[start + t + 3]);
        float4 v0 = embW4[i0.y * 16 + q];
        float4 v1 = embW4[i1.y * 16 + q];
        float4 v2 = embW4[i2.y * 16 + q];
        float4 v3 = embW4[i3.y * 16 + q];
        acc = f4add(acc, f4add(f4add(v0, v1), f4add(v2, v3)));
    }
    for (; t < cnt; t++) {
        int2 i0 = __ldg(&g_sx[start + t]);
        acc = f4add(acc, embW4[i0.y * 16 + q]);
    }
    acc.x = fmaxf(acc.x, 0.f); acc.y = fmaxf(acc.y, 0.f);
    acc.z = fmaxf(acc.z, 0.f); acc.w = fmaxf(acc.w, 0.f);
    reinterpret_cast<float4*>(g_h1 + node * D)[q] = acc;
}

// ---------------- SAGE gather: nb[n] = mean_nb h1[src] (idx prefetch pipeline) ----------
__global__ void k_gather_mean(int n_nodes) {
    int gid = blockIdx.x * blockDim.x + threadIdx.x;
    int node = gid >> 4, q = gid & 15;
    if (node >= n_nodes) return;
    int start = g_off[node];
    int cnt = g_off[node + 1] - start;
    float4 acc = make_float4(0.f, 0.f, 0.f, 0.f);
    int t = 0;
    if (cnt >= 4) {
        int2 c0 = __ldg(&g_sx[start + 0]);
        int2 c1 = __ldg(&g_sx[start + 1]);
        int2 c2 = __ldg(&g_sx[start + 2]);
        int2 c3 = __ldg(&g_sx[start + 3]);
        for (; t + 8 <= cnt; t += 4) {
            int2 n0 = __ldg(&g_sx[start + t + 4]);
            int2 n1 = __ldg(&g_sx[start + t + 5]);
            int2 n2 = __ldg(&g_sx[start + t + 6]);
            int2 n3 = __ldg(&g_sx[start + t + 7]);
            float4 v0 = reinterpret_cast<const float4*>(g_h1 + c0.x * D)[q];
            float4 v1 = reinterpret_cast<const float4*>(g_h1 + c1.x * D)[q];
            float4 v2 = reinterpret_cast<const float4*>(g_h1 + c2.x * D)[q];
            float4 v3 = reinterpret_cast<const float4*>(g_h1 + c3.x * D)[q];
            acc = f4add(acc, f4add(f4add(v0, v1), f4add(v2, v3)));
            c0 = n0; c1 = n1; c2 = n2; c3 = n3;
        }
        // drain the last prefetched batch
        float4 v0 = reinterpret_cast<const float4*>(g_h1 + c0.x * D)[q];
        float4 v1 = reinterpret_cast<const float4*>(g_h1 + c1.x * D)[q];
        float4 v2 = reinterpret_cast<const float4*>(g_h1 + c2.x * D)[q];
        float4 v3 = reinterpret_cast<const float4*>(g_h1 + c3.x * D)[q];
        acc = f4add(acc, f4add(f4add(v0, v1), f4add(v2, v3)));
        t += 4;
    }
    for (; t < cnt; t++) {
        int2 i0 = __ldg(&g_sx[start + t]);
        acc = f4add(acc, reinterpret_cast<const float4*>(g_h1 + i0.x * D)[q]);
    }
    float invd = 1.0f / fmaxf((float)cnt, 1.0f);
    acc.x *= invd; acc.y *= invd; acc.z *= invd; acc.w *= invd;
    reinterpret_cast<float4*>(g_nb + node * D)[q] = acc;
}

// ---------------- GIN gather: z[n] = h2[n] + sum_nb h2[src] (idx prefetch pipeline) -------
__global__ void k_gather_gin(int n_nodes) {
    int gid = blockIdx.x * blockDim.x + threadIdx.x;
    int node = gid >> 4, q = gid & 15;
    if (node >= n_nodes) return;
    int start = g_off[node];
    int cnt = g_off[node + 1] - start;
    float4 acc = reinterpret_cast<const float4*>(g_h2 + node * D)[q];
    int t = 0;
    if (cnt >= 4) {
        int2 c0 = __ldg(&g_sx[start + 0]);
        int2 c1 = __ldg(&g_sx[start + 1]);
        int2 c2 = __ldg(&g_sx[start + 2]);
        int2 c3 = __ldg(&g_sx[start + 3]);
        for (; t + 8 <= cnt; t += 4) {
            int2 n0 = __ldg(&g_sx[start + t + 4]);
            int2 n1 = __ldg(&g_sx[start + t + 5]);
            int2 n2 = __ldg(&g_sx[start + t + 6]);
            int2 n3 = __ldg(&g_sx[start + t + 7]);
            float4 v0 = reinterpret_cast<const float4*>(g_h2 + c0.x * D)[q];
            float4 v1 = reinterpret_cast<const float4*>(g_h2 + c1.x * D)[q];
            float4 v2 = reinterpret_cast<const float4*>(g_h2 + c2.x * D)[q];
            float4 v3 = reinterpret_cast<const float4*>(g_h2 + c3.x * D)[q];
            acc = f4add(acc, f4add(f4add(v0, v1), f4add(v2, v3)));
            c0 = n0; c1 = n1; c2 = n2; c3 = n3;
        }
        float4 v0 = reinterpret_cast<const float4*>(g_h2 + c0.x * D)[q];
        float4 v1 = reinterpret_cast<const float4*>(g_h2 + c1.x * D)[q];
        float4 v2 = reinterpret_cast<const float4*>(g_h2 + c2.x * D)[q];
        float4 v3 = reinterpret_cast<const float4*>(g_h2 + c3.x * D)[q];
        acc = f4add(acc, f4add(f4add(v0, v1), f4add(v2, v3)));
        t += 4;
    }
    for (; t < cnt; t++) {
        int2 i0 = __ldg(&g_sx[start + t]);
        acc = f4add(acc, reinterpret_cast<const float4*>(g_h2 + i0.x * D)[q]);
    }
    reinterpret_cast<float4*>(g_z + node * D)[q] = acc;
}

// ---------------- SAGE GEMM: h2 = relu(nb @ Wl + h1 @ Wr) ----------------
__global__ void __launch_bounds__(256) k_sage(const float* __restrict__ Wl,
                                              const float* __restrict__ Wr, int n_nodes) {
    __shared__ ulonglong2 sWl[D * 16];
    __shared__ ulonglong2 sWr[D * 16];
    {
        const ulonglong2* wl2 = reinterpret_cast<const ulonglong2*>(Wl);
        const ulonglong2* wr2 = reinterpret_cast<const ulonglong2*>(Wr);
        for (int i = threadIdx.x; i < D * 16; i += blockDim.x) { sWl[i] = wl2[i]; sWr[i] = wr2[i]; }
    }
    __syncthreads();
    int lane = threadIdx.x & 31, warp = threadIdx.x >> 5;
    int ntiles = (n_nodes + 31) / 32;
    int nwarps = gridDim.x * 8;
    for (int tile = blockIdx.x * 8 + warp; tile < ntiles; tile += nwarps) {
        int n = tile * 32 + lane;
        bool valid = n < n_nodes;
        int nn = valid ? n : (n_nodes - 1);
        const float4* nb4 = reinterpret_cast<const float4*>(g_nb + nn * D);
        const float4* h4 = reinterpret_cast<const float4*>(g_h1 + nn * D);
        u64 acc[32];
#pragma unroll
        for (int j = 0; j < 32; j++) acc[j] = 0ULL;
        for (int kk = 0; kk < 16; kk++) {
            float4 anb = __ldg(nb4 + kk);
            float4 ah = __ldg(h4 + kk);
            float an[4] = {anb.x, anb.y, anb.z, anb.w};
            float av[4] = {ah.x, ah.y, ah.z, ah.w};
#pragma unroll
            for (int s = 0; s < 4; s++) {
                int k = kk * 4 + s;
                u64 pa = pack2s(an[s]);
                u64 ph = pack2s(av[s]);
#pragma unroll
                for (int jj = 0; jj < 16; jj++) {
                    ulonglong2 wl = sWl[k * 16 + jj];
                    ulonglong2 wr = sWr[k * 16 + jj];
                    ffma2(acc[2 * jj], pa, wl.x);
                    ffma2(acc[2 * jj], ph, wr.x);
                    ffma2(acc[2 * jj + 1], pa, wl.y);
                    ffma2(acc[2 * jj + 1], ph, wr.y);
                }
            }
        }
        if (valid) {
            float4* o = reinterpret_cast<float4*>(g_h2 + n * D);
#pragma unroll
            for (int jj = 0; jj < 16; jj++) {
                float2 p0 = unpack2(acc[2 * jj]);
                float2 p1 = unpack2(acc[2 * jj + 1]);
                o[jj] = make_float4(fmaxf(p0.x, 0.f), fmaxf(p0.y, 0.f),
                                    fmaxf(p1.x, 0.f), fmaxf(p1.y, 0.f));
            }
        }
    }
}

// ---------------- GIN GEMM: h3 = relu(relu(z@W1+b1)@W2+b2) ----------------
__global__ void __launch_bounds__(256) k_gin(const float* __restrict__ W1,
                                             const float* __restrict__ b1,
                                             const float* __restrict__ W2,
                                             const float* __restrict__ b2, int n_nodes) {
    __shared__ ulonglong2 sW1[D * 16];
    __shared__ ulonglong2 sW2[D * 16];
    {
        const ulonglong2* w12 = reinterpret_cast<const ulonglong2*>(W1);
        const ulonglong2* w22 = reinterpret_cast<const ulonglong2*>(W2);
        for (int i = threadIdx.x; i < D * 16; i += blockDim.x) { sW1[i] = w12[i]; sW2[i] = w22[i]; }
    }
    __syncthreads();
    int lane = threadIdx.x & 31, warp = threadIdx.x >> 5;
    int ntiles = (n_nodes + 31) / 32;
    int nwarps = gridDim.x * 8;
    const float4* b1v = reinterpret_cast<const float4*>(b1);
    const float4* b2v = reinterpret_cast<const float4*>(b2);
    for (int tile = blockIdx.x * 8 + warp; tile < ntiles; tile += nwarps) {
        int n = tile * 32 + lane;
        bool valid = n < n_nodes;
        int nn = valid ? n : (n_nodes - 1);
        const float4* z4 = reinterpret_cast<const float4*>(g_z + nn * D);
        u64 acc[32];
#pragma unroll
        for (int jj = 0; jj < 16; jj++) {
            float4 bb = __ldg(b1v + jj);
            acc[2 * jj] = pack2(bb.x, bb.y);
            acc[2 * jj + 1] = pack2(bb.z, bb.w);
        }
        for (int kk = 0; kk < 16; kk++) {
            float4 az = __ldg(z4 + kk);
            float av[4] = {az.x, az.y, az.z, az.w};
#pragma unroll
            for (int s = 0; s < 4; s++) {
                int k = kk * 4 + s;
                u64 pz = pack2s(av[s]);
#pragma unroll
                for (int jj = 0; jj < 16; jj++) {
                    ulonglong2 w = sW1[k * 16 + jj];
                    ffma2(acc[2 * jj], pz, w.x);
                    ffma2(acc[2 * jj + 1], pz, w.y);
                }
            }
        }
        {
            float4* tstage = reinterpret_cast<float4*>(g_nb + nn * D);
#pragma unroll
            for (int jj = 0; jj < 16; jj++) {
                float2 p0 = unpack2(acc[2 * jj]);
                float2 p1 = unpack2(acc[2 * jj + 1]);
                tstage[jj] = make_float4(fmaxf(p0.x, 0.f), fmaxf(p0.y, 0.f),
                                         fmaxf(p1.x, 0.f), fmaxf(p1.y, 0.f));
            }
        }
#pragma unroll
        for (int jj = 0; jj < 16; jj++) {
            float4 bb = __ldg(b2v + jj);
            acc[2 * jj] = pack2(bb.x, bb.y);
            acc[2 * jj + 1] = pack2(bb.z, bb.w);
        }
        const float4* t4 = reinterpret_cast<const float4*>(g_nb + nn * D);
        for (int kk = 0; kk < 16; kk++) {
            float4 at = t4[kk];
            float av[4] = {at.x, at.y, at.z, at.w};
#pragma unroll
            for (int s = 0; s < 4; s++) {
                int k = kk * 4 + s;
                u64 pt = pack2s(av[s]);
#pragma unroll
                for (int jj = 0; jj < 16; jj++) {
                    ulonglong2 w = sW2[k * 16 + jj];
                    ffma2(acc[2 * jj], pt, w.x);
                    ffma2(acc[2 * jj + 1], pt, w.y);
                }
            }
        }
        if (valid) {
            float4* o = reinterpret_cast<float4*>(g_h3 + n * D);
#pragma unroll
            for (int jj = 0; jj < 16; jj++) {
                float2 p0 = unpack2(acc[2 * jj]);
                float2 p1 = unpack2(acc[2 * jj + 1]);
                o[jj] = make_float4(fmaxf(p0.x, 0.f), fmaxf(p0.y, 0.f),
                                    fmaxf(p1.x, 0.f), fmaxf(p1.y, 0.f));
            }
        }
    }
}

// ---------------- fused pool+final: warp per graph; batch is SORTED ----------------
__global__ void __launch_bounds__(128) k_final2(const int* __restrict__ batch,
                                                const float* __restrict__ Wp1,
                                                const float* __restrict__ Wp2,
                                                const float* __restrict__ Wp3,
                                                float* __restrict__ out, int Gn, int n_nodes) {
    __shared__ float s1[D * D];
    __shared__ float s2[D * D];
    __shared__ float s3[D * D];
    for (int i = threadIdx.x; i < D * D; i += blockDim.x) { s1[i] = Wp1[i]; s2[i] = Wp2[i]; s3[i] = Wp3[i]; }
    __syncthreads();
    int warp = threadIdx.x >> 5, lane = threadIdx.x & 31;
    int g = blockIdx.x * 4 + warp;
    if (g >= Gn) return;
    int lo = 0, hi = n_nodes;
    while (lo < hi) { int mid = (lo + hi) >> 1; if (__ldg(&batch[mid]) < g) lo = mid + 1; else hi = mid; }
    int start = lo;
    hi = n_nodes;
    while (lo < hi) { int mid = (lo + hi) >> 1; if (__ldg(&batch[mid]) < g + 1) lo = mid + 1; else hi = mid; }
    int end = lo;
    float ic = 1.0f / fmaxf((float)(end - start), 1.0f);
    float a0 = 0.f, a1 = 0.f, b0 = 0.f, b1 = 0.f, c0 = 0.f, c1 = 0.f;
    float a0b = 0.f, a1b = 0.f, b0b = 0.f, b1b = 0.f, c0b = 0.f, c1b = 0.f;
    int nn = start;
    for (; nn + 2 <= end; nn += 2) {
        a0 += g_h1[nn * D + lane];  a1 += g_h1[nn * D + lane + 32];
        b0 += g_h2[nn * D + lane];  b1 += g_h2[nn * D + lane + 32];
        c0 += g_h3[nn * D + lane];  c1 += g_h3[nn * D + lane + 32];
        a0b += g_h1[(nn + 1) * D + lane];  a1b += g_h1[(nn + 1) * D + lane + 32];
        b0b += g_h2[(nn + 1) * D + lane];  b1b += g_h2[(nn + 1) * D + lane + 32];
        c0b += g_h3[(nn + 1) * D + lane];  c1b += g_h3[(nn + 1) * D + lane + 32];
    }
    for (; nn < end; nn++) {
        a0 += g_h1[nn * D + lane];  a1 += g_h1[nn * D + lane + 32];
        b0 += g_h2[nn * D + lane];  b1 += g_h2[nn * D + lane + 32];
        c0 += g_h3[nn * D + lane];  c1 += g_h3[nn * D + lane + 32];
    }
    a0 = (a0 + a0b) * ic; a1 = (a1 + a1b) * ic;
    b0 = (b0 + b0b) * ic; b1 = (b1 + b1b) * ic;
    c0 = (c0 + c0b) * ic; c1 = (c1 + c1b) * ic;
    float acc0 = 0.f, acc1 = 0.f;
#pragma unroll
    for (int k = 0; k < 32; k++) {
        float va = __shfl_sync(0xffffffffu, a0, k);
        float vb = __shfl_sync(0xffffffffu, b0, k);
        float vc = __shfl_sync(0xffffffffu, c0, k);
        acc0 += va * s1[k * D + lane] + vb * s2[k * D + lane] + vc * s3[k * D + lane];
        acc1 += va * s1[k * D + lane + 32] + vb * s2[k * D + lane + 32] + vc * s3[k * D + lane + 32];
    }
#pragma unroll
    for (int k = 0; k < 32; k++) {
        float va = __shfl_sync(0xffffffffu, a1, k);
        float vb = __shfl_sync(0xffffffffu, b1, k);
        float vc = __shfl_sync(0xffffffffu, c1, k);
        acc0 += va * s1[(k + 32) * D + lane] + vb * s2[(k + 32) * D + lane] + vc * s3[(k + 32) * D + lane];
        acc1 += va * s1[(k + 32) * D + lane + 32] + vb * s2[(k + 32) * D + lane + 32] + vc * s3[(k + 32) * D + lane + 32];
    }
    out[g * D + lane] = fmaxf(acc0, 0.f);
    out[g * D + lane + 32] = fmaxf(acc1, 0.f);
}

// ---------------- launch ----------------
extern "C" void kernel_launch(void* const* d_in, const int* in_sizes, int n_in,
                              void* d_out, int out_size) {
    const int* x      = (const int*)d_in[0];
    const int* ei     = (const int*)d_in[1];
    const int* batch  = (const int*)d_in[2];
    const float* emb  = (const float*)d_in[3];
    const float* Wgcn = (const float*)d_in[4];
    const float* Wsl  = (const float*)d_in[5];
    const float* Wsr  = (const float*)d_in[6];
    const float* Wg1  = (const float*)d_in[7];
    const float* bg1  = (const float*)d_in[8];
    const float* Wg2  = (const float*)d_in[9];
    const float* bg2  = (const float*)d_in[10];
    const float* Wp1  = (const float*)d_in[11];
    const float* Wp2  = (const float*)d_in[12];
    const float* Wp3  = (const float*)d_in[13];
    float* out = (float*)d_out;

    int n = in_sizes[0];
    int e = in_sizes[1] / 2;
    int v = in_sizes[3] / D;
    int g = out_size / D;

    int preblk = (e / 8 + 255) / 256;
    k_pre<<<preblk, 256>>>(ei, emb, Wgcn, v, e);
    k_scan<<<1, 1024>>>(n);
    k_scatter<<<(e / 4 + 255) / 256, 256>>>(ei, x, e);

    int gth = n * 16;
    int gblk = (gth + 255) / 256;
    k_gather_gcn<<<gblk, 256>>>(n);
    k_gather_mean<<<gblk, 256>>>(n);

    int ntiles = (n + 31) / 32;
    int ggrid = (ntiles + 7) / 8;
    k_sage<<<ggrid, 256>>>(Wsl, Wsr, n);
    k_gather_gin<<<gblk, 256>>>(n);
    k_gin<<<ggrid, 256>>>(Wg1, bg1, Wg2, bg2, n);
    k_final2<<<(g + 3) / 4, 128>>>(batch, Wp1, Wp2, Wp3, out, g, n);
}